// round 2
// baseline (speedup 1.0000x reference)
#include <cuda_runtime.h>

// Problem shape (fixed by the reference):
//   a, b, h : (B=2, S=2048, D=1024, N=16) float32, row-major.
// Recurrence along S: h[t] = a[t]*h[t-1] + b[t], h[-1]=0.
// B*D*N = 32768 independent channels; scan stride = D*N floats.

static constexpr int S_LEN  = 2048;
static constexpr int STRIDE = 1024 * 16;      // D*N
static constexpr int CHANNELS = 2 * STRIDE;   // B*D*N = 32768
static constexpr int UNROLL = 8;

__global__ __launch_bounds__(256, 1)
void ParallelScan_37374805409922_kernel(const float* __restrict__ a,
                                        const float* __restrict__ b,
                                        float* __restrict__ out) {
    const int idx = blockIdx.x * blockDim.x + threadIdx.x;   // channel id, 0..32767
    const int batch = idx / STRIDE;
    const int col   = idx - batch * STRIDE;
    // Base offset for this channel at t=0. Max index = 2*2048*16384 < 2^31, int is safe.
    const int base = batch * (S_LEN * STRIDE) + col;

    const float* __restrict__ ap = a + base;
    const float* __restrict__ bp = b + base;
    float* __restrict__ op = out + base;

    float h = 0.0f;

    #pragma unroll 1
    for (int t = 0; t < S_LEN; t += UNROLL) {
        // Batch all loads for this group first: 16 independent LDGs in flight
        // per thread -> DRAM latency hidden across 8 warps/SM.
        float av[UNROLL], bv[UNROLL];
        #pragma unroll
        for (int u = 0; u < UNROLL; u++) {
            const int off = (t + u) * STRIDE;
            av[u] = ap[off];
            bv[u] = bp[off];
        }
        // Serial dependency chain (4-cycle FFMA latency each) + coalesced stores.
        #pragma unroll
        for (int u = 0; u < UNROLL; u++) {
            h = fmaf(av[u], h, bv[u]);
            op[(t + u) * STRIDE] = h;
        }
    }
}

extern "C" void kernel_launch(void* const* d_in, const int* in_sizes, int n_in,
                              void* d_out, int out_size) {
    const float* a = (const float*)d_in[0];
    const float* b = (const float*)d_in[1];
    float* out = (float*)d_out;
    (void)in_sizes; (void)n_in; (void)out_size;

    // 32768 channels -> 128 blocks x 256 threads: one wave, 8 warps/SM on 128 SMs.
    ParallelScan_37374805409922_kernel<<<CHANNELS / 256, 256>>>(a, b, out);
}

// round 3
// speedup vs baseline: 1.6345x; 1.6345x over previous
#include <cuda_runtime.h>

// Shape: a, b, h : (B=2, S=2048, D=1024, N=16) fp32, row-major.
// h[t] = a[t]*h[t-1] + b[t] along S. B*D*N = 32768 independent channels,
// contiguous at fixed t; scan stride = D*N = 16384 floats (64 KB).
//
// Strategy: one thread per channel, double-buffered register pipeline so the
// next group's 32 loads are in flight while the current group's serial FMA
// chain runs. Chip-wide in-flight bytes = 32768 thr * 128 B = 4 MB, above the
// ~2 MB BW*latency product -> DRAM-bandwidth-bound (~768 MB total traffic).

static constexpr int S_LEN  = 2048;
static constexpr int STRIDE = 1024 * 16;        // D*N floats between timesteps
static constexpr int CHANNELS = 2 * STRIDE;     // 32768
static constexpr int U = 16;                    // timesteps per pipeline stage
static constexpr int N_IT = S_LEN / (2 * U);    // 64 outer iterations

__global__ __launch_bounds__(256, 1)
void ParallelScan_37374805409922_kernel(const float* __restrict__ a,
                                        const float* __restrict__ b,
                                        float* __restrict__ out) {
    const int idx   = blockIdx.x * blockDim.x + threadIdx.x;  // 0..32767
    const int batch = idx >> 14;            // / 16384
    const int col   = idx & (STRIDE - 1);
    const size_t base = (size_t)batch * S_LEN * STRIDE + col;

    const float* __restrict__ ap = a + base;
    const float* __restrict__ bp = b + base;
    float* __restrict__ op = out + base;

    float a0[U], b0[U], a1[U], b1[U];

    // Prologue: group 0 -> buffer 0.
    #pragma unroll
    for (int u = 0; u < U; u++) {
        a0[u] = __ldcs(ap + u * STRIDE);
        b0[u] = __ldcs(bp + u * STRIDE);
    }

    float h = 0.0f;

    #pragma unroll 1
    for (int it = 0; it < N_IT; it++) {
        // Prefetch group (2*it + 1) -> buffer 1 (always in range).
        #pragma unroll
        for (int u = 0; u < U; u++) {
            a1[u] = __ldcs(ap + (U + u) * STRIDE);
            b1[u] = __ldcs(bp + (U + u) * STRIDE);
        }

        // Consume buffer 0: timesteps [2*it*U, 2*it*U + U).
        #pragma unroll
        for (int u = 0; u < U; u++) {
            h = fmaf(a0[u], h, b0[u]);
            __stcs(op + u * STRIDE, h);
        }

        // Prefetch group (2*it + 2) -> buffer 0 (skip on final iteration).
        if (it + 1 < N_IT) {
            #pragma unroll
            for (int u = 0; u < U; u++) {
                a0[u] = __ldcs(ap + (2 * U + u) * STRIDE);
                b0[u] = __ldcs(bp + (2 * U + u) * STRIDE);
            }
        }

        // Consume buffer 1: timesteps [2*it*U + U, 2*it*U + 2*U).
        #pragma unroll
        for (int u = 0; u < U; u++) {
            h = fmaf(a1[u], h, b1[u]);
            __stcs(op + (U + u) * STRIDE, h);
        }

        ap += 2 * U * STRIDE;
        bp += 2 * U * STRIDE;
        op += 2 * U * STRIDE;
    }
}

extern "C" void kernel_launch(void* const* d_in, const int* in_sizes, int n_in,
                              void* d_out, int out_size) {
    const float* a = (const float*)d_in[0];
    const float* b = (const float*)d_in[1];
    float* out = (float*)d_out;
    (void)in_sizes; (void)n_in; (void)out_size;

    ParallelScan_37374805409922_kernel<<<CHANNELS / 256, 256>>>(a, b, out);
}

// round 4
// speedup vs baseline: 1.8462x; 1.1295x over previous
#include <cuda_runtime.h>

// Shape: a, b, h : (B=2, S=2048, D=1024, N=16) fp32, row-major.
// h[t] = a[t]*h[t-1] + b[t] along S. B*D*N = 32768 independent channels,
// contiguous at fixed t; scan stride = D*N = 16384 floats.
//
// R3: prefetch-distance-2 register pipeline (4 rotating buffers of U=16
// timesteps). Peak ~55 outstanding LDGs/warp (HW cap) = ~7 KB in flight per
// warp, ~7 MB chip-wide -> above the ~3.6 MB BW*latency product at NAT
// clocks -> DRAM-bandwidth-bound.

static constexpr int S_LEN   = 2048;
static constexpr int STRIDE  = 1024 * 16;       // D*N floats between timesteps
static constexpr int CHANNELS = 2 * STRIDE;     // 32768
static constexpr int U       = 16;              // timesteps per group
static constexpr int N_GROUPS = S_LEN / U;      // 128
static constexpr int N_SUPER  = N_GROUPS / 4;   // 32 super-iterations (4 groups each)

// Load group G (local, relative to current ap/bp) into buffers A/B.
#define PREF(A, B, G)                                            \
    _Pragma("unroll")                                            \
    for (int u = 0; u < U; u++) {                                \
        A[u] = __ldcs(ap + ((G) * U + u) * STRIDE);              \
        B[u] = __ldcs(bp + ((G) * U + u) * STRIDE);              \
    }

// Consume buffers A/B as local group G: serial FMA chain + streaming stores.
#define CONS(A, B, G)                                            \
    _Pragma("unroll")                                            \
    for (int u = 0; u < U; u++) {                                \
        h = fmaf(A[u], h, B[u]);                                 \
        __stcs(op + ((G) * U + u) * STRIDE, h);                  \
    }

__global__ __launch_bounds__(256, 1)
void ParallelScan_37374805409922_kernel(const float* __restrict__ a,
                                        const float* __restrict__ b,
                                        float* __restrict__ out) {
    const int idx   = blockIdx.x * blockDim.x + threadIdx.x;  // 0..32767
    const int batch = idx >> 14;                               // / 16384
    const int col   = idx & (STRIDE - 1);
    const size_t base = (size_t)batch * S_LEN * STRIDE + col;

    const float* __restrict__ ap = a + base;
    const float* __restrict__ bp = b + base;
    float* __restrict__ op = out + base;

    float a0[U], b0[U], a1[U], b1[U], a2[U], b2[U], a3[U], b3[U];
    float h = 0.0f;

    // Prologue: groups 0 and 1 in flight before any consumption.
    PREF(a0, b0, 0)
    PREF(a1, b1, 1)

    #pragma unroll 1
    for (int s = 0; s < N_SUPER; s++) {
        // Steady state: always 2 groups of loads ahead of the consume point.
        PREF(a2, b2, 2)
        CONS(a0, b0, 0)

        PREF(a3, b3, 3)
        CONS(a1, b1, 1)

        if (s + 1 < N_SUPER) {
            PREF(a0, b0, 4)
        }
        CONS(a2, b2, 2)

        if (s + 1 < N_SUPER) {
            PREF(a1, b1, 5)
        }
        CONS(a3, b3, 3)

        ap += 4 * U * STRIDE;
        bp += 4 * U * STRIDE;
        op += 4 * U * STRIDE;
    }
}

extern "C" void kernel_launch(void* const* d_in, const int* in_sizes, int n_in,
                              void* d_out, int out_size) {
    const float* a = (const float*)d_in[0];
    const float* b = (const float*)d_in[1];
    float* out = (float*)d_out;
    (void)in_sizes; (void)n_in; (void)out_size;

    ParallelScan_37374805409922_kernel<<<CHANNELS / 256, 256>>>(a, b, out);
}